// round 2
// baseline (speedup 1.0000x reference)
#include <cuda_runtime.h>
#include <stdint.h>

// YOLACT-550 Fast-NMS, GB300 sm_103a
// B=16, C=80, N=19248, TOP_K=200
// One CTA per (image, class) row: smem-staged bisection top-k select,
// bitonic sort of <=1024 candidates, upper-triangular IoU-max, pack output.

#define NB 16
#define NC 80
#define NN 19248
#define NV4 4812          // NN / 4
#define KTOP 200
#define CAP 1024          // max candidates kept for the sort
#define NT 256

// smem layout (bytes):
// [0, 76992)           : score bits, uint32[19248]  (reused later for box SoA)
// [76992, 85184)       : cand, uint64[1024]
// [85184, 85184+256)   : reduction scratch
#define OFF_CAND 76992
#define OFF_RED  (76992 + 8192)
#define SMEM_BYTES (OFF_RED + 256)

__global__ __launch_bounds__(NT, 2)
void fastnms_kernel(const float* __restrict__ boxes_raw,
                    const float* __restrict__ scores,
                    float* __restrict__ out)
{
    extern __shared__ unsigned char smraw[];
    uint32_t*           sbits = reinterpret_cast<uint32_t*>(smraw);
    unsigned long long* cand  = reinterpret_cast<unsigned long long*>(smraw + OFF_CAND);
    uint32_t*           red   = reinterpret_cast<uint32_t*>(smraw + OFF_RED);

    const int tid  = threadIdx.x;
    const int lane = tid & 31;
    const int wid  = tid >> 5;
    const int bc   = blockIdx.x;          // b*NC + c
    const int b    = bc / NC;

    // ---------------- 1. Stage score row into smem, compute max ----------------
    const uint4* srow4 = reinterpret_cast<const uint4*>(scores + (size_t)bc * NN);
    uint4*       sb4   = reinterpret_cast<uint4*>(sbits);

    uint32_t mymax = 0u;
    for (int i = tid; i < NV4; i += NT) {
        uint4 v = srow4[i];
        sb4[i] = v;
        mymax = max(mymax, max(max(v.x, v.y), max(v.z, v.w)));
    }
    #pragma unroll
    for (int o = 16; o; o >>= 1)
        mymax = max(mymax, __shfl_xor_sync(0xFFFFFFFFu, mymax, o));
    if (lane == 0) red[wid] = mymax;
    __syncthreads();
    if (tid == 0) {
        uint32_t m = red[0];
        #pragma unroll
        for (int w = 1; w < NT / 32; ++w) m = max(m, red[w]);
        red[16] = m;
    }
    __syncthreads();

    // ---------------- 2. Bisection select: find T with 200 <= #{>=T} <= CAP -----
    // Scores are non-negative floats: raw-bit unsigned compare preserves order.
    uint32_t lo = 0u, hi = red[16];
    uint32_t T = 0u;           // fallback: keep everything (ge(0) = NN)
    int bestGe = NN;

    for (int it = 0; it < 32; ++it) {
        if (lo > hi) break;
        uint32_t t = lo + ((hi - lo) >> 1);

        int c = 0;
        for (int i = tid; i < NV4; i += NT) {
            uint4 v = sb4[i];
            c += (v.x >= t) + (v.y >= t) + (v.z >= t) + (v.w >= t);
        }
        #pragma unroll
        for (int o = 16; o; o >>= 1) c += __shfl_down_sync(0xFFFFFFFFu, c, o);
        __syncthreads();                 // protect red[] from previous iteration
        if (lane == 0) red[wid] = (uint32_t)c;
        __syncthreads();
        if (tid == 0) {
            int s = 0;
            #pragma unroll
            for (int w = 0; w < NT / 32; ++w) s += (int)red[w];
            red[17] = (uint32_t)s;
        }
        __syncthreads();
        int ge = (int)red[17];           // identical across all threads

        if (ge >= KTOP) {
            if (ge < bestGe) { bestGe = ge; T = t; }
            if (ge <= CAP) break;        // window hit
            lo = t + 1;
        } else {
            if (t == 0) break;
            hi = t - 1;
        }
    }

    // ---------------- 3. Collect survivors as (valbits, ~idx) keys --------------
    if (tid == 0) red[18] = 0u;
    __syncthreads();
    for (int i = tid; i < NN; i += NT) {
        uint32_t v = sbits[i];
        if (v >= T) {
            int pos = atomicAdd(reinterpret_cast<int*>(&red[18]), 1);
            if (pos < CAP)
                cand[pos] = ((unsigned long long)v << 32)
                          | (unsigned long long)(0xFFFFFFFFu - (uint32_t)i);
        }
    }
    __syncthreads();
    int M = min((int)red[18], CAP);      // M >= 200 guaranteed (ge(0) = NN)

    // ---------------- 4. Bitonic sort descending (pad to pow2 with 0) -----------
    int S = 256;
    while (S < M) S <<= 1;               // S in {256, 512, 1024}
    for (int i = M + tid; i < S; i += NT) cand[i] = 0ull;
    __syncthreads();

    for (int k = 2; k <= S; k <<= 1) {
        for (int j = k >> 1; j > 0; j >>= 1) {
            for (int i = tid; i < S; i += NT) {
                int ixj = i ^ j;
                if (ixj > i) {
                    unsigned long long a  = cand[i];
                    unsigned long long c2 = cand[ixj];
                    bool desc = ((i & k) == 0);
                    if ((a < c2) == desc) { cand[i] = c2; cand[ixj] = a; }
                }
            }
            __syncthreads();
        }
    }

    // ---------------- 5. Gather + decode boxes (alias dead sbits region) --------
    float* sx1 = reinterpret_cast<float*>(smraw);
    float* sy1 = sx1 + 256;
    float* sx2 = sx1 + 512;
    float* sy2 = sx1 + 768;
    float* sar = sx1 + 1024;

    float x1 = 0.f, y1v = 0.f, x2 = 0.f, y2v = 0.f, area = 0.f, sc = 0.f;
    if (tid < KTOP) {
        unsigned long long key = cand[tid];
        uint32_t idx = 0xFFFFFFFFu - (uint32_t)(key & 0xFFFFFFFFull);
        sc = __uint_as_float((uint32_t)(key >> 32));
        float4 rb = reinterpret_cast<const float4*>(boxes_raw)[(size_t)b * NN + idx];
        float w  = rb.z * 0.5f + 1e-2f;
        float h  = rb.w * 0.5f + 1e-2f;
        float hw = 0.5f * w, hh = 0.5f * h;
        x1  = rb.x - hw;  x2  = rb.x + hw;
        y1v = rb.y - hh;  y2v = rb.y + hh;
        area = (x2 - x1) * (y2v - y1v);   // match reference: area from corners
        sx1[tid] = x1;  sy1[tid] = y1v;
        sx2[tid] = x2;  sy2[tid] = y2v;
        sar[tid] = area;
    }
    __syncthreads();

    // ---------------- 6. IoU max against higher-scored boxes, pack output -------
    if (tid < KTOP) {
        float imax = 0.f;
        for (int i = 0; i < tid; ++i) {   // broadcast smem reads across the warp
            float xx1 = fmaxf(x1,  sx1[i]);
            float yy1 = fmaxf(y1v, sy1[i]);
            float xx2 = fminf(x2,  sx2[i]);
            float yy2 = fminf(y2v, sy2[i]);
            float iw  = fmaxf(xx2 - xx1, 0.f);
            float ih  = fmaxf(yy2 - yy1, 0.f);
            float inter = iw * ih;
            float uni   = area + sar[i] - inter;
            imax = fmaxf(imax, inter / uni);
        }
        float osc = (imax <= 0.5f && sc > 0.05f) ? sc : 0.f;
        size_t o = ((size_t)bc * KTOP + (size_t)tid) * 5;
        out[o + 0] = osc;
        out[o + 1] = x1;
        out[o + 2] = y1v;
        out[o + 3] = x2;
        out[o + 4] = y2v;
    }
}

extern "C" void kernel_launch(void* const* d_in, const int* in_sizes, int n_in,
                              void* d_out, int out_size)
{
    const float* boxes  = (const float*)d_in[0];
    const float* scores = (const float*)d_in[1];
    // Defensive: boxes tensor (B*N*4 = 1,231,872) is smaller than scores
    // (B*C*N = 24,637,440); swap if metadata order differs.
    if (n_in >= 2 && in_sizes[0] > in_sizes[1]) {
        boxes  = (const float*)d_in[1];
        scores = (const float*)d_in[0];
    }
    (void)out_size;

    cudaFuncSetAttribute(fastnms_kernel,
                         cudaFuncAttributeMaxDynamicSharedMemorySize, SMEM_BYTES);
    fastnms_kernel<<<NB * NC, NT, SMEM_BYTES>>>(boxes, scores, (float*)d_out);
}

// round 3
// speedup vs baseline: 2.6674x; 2.6674x over previous
#include <cuda_runtime.h>
#include <stdint.h>

// YOLACT-550 Fast-NMS, GB300 sm_103a — round 2
// B=16, C=80, N=19248, TOP_K=200
// One CTA per (image, class) row. Single-pass threshold collection from
// global (statistical threshold, exact-fallback bisection), small-smem
// bitonic sort, triangular IoU-max, pack.

#define NB   16
#define NC   80
#define NN   19248
#define NV4  4812            // NN/4
#define NPAD 4864            // ceil(NV4/256)*256 -> uniform warp loop for ballots
#define KTOP 200
#define CAP  1024
#define NT   256

__device__ __forceinline__ unsigned long long mk_key(uint32_t v, uint32_t idx) {
    // descending value, ascending index on ties (matches jax.lax.top_k)
    return ((unsigned long long)v << 32) | (unsigned long long)(0xFFFFFFFFu - idx);
}

__global__ __launch_bounds__(NT, 6)
void fastnms_kernel(const float* __restrict__ boxes_raw,
                    const float* __restrict__ scores,
                    float* __restrict__ out)
{
    __shared__ unsigned long long cand[CAP];
    __shared__ float sbox[5][KTOP];       // x1,y1,x2,y2,area
    __shared__ uint32_t red[32];
    __shared__ int scnt;

    const int tid  = threadIdx.x;
    const int lane = tid & 31;
    const int wid  = tid >> 5;
    const int bc   = blockIdx.x;          // b*NC + c
    const int b    = bc / NC;

    const uint4* srow = reinterpret_cast<const uint4*>(scores) + (size_t)bc * NV4;

    // ---------------- 1. One-pass collection at statistical threshold ----------
    // Scores are non-negative floats: raw-bit unsigned compare == float compare.
    uint32_t T = __float_as_uint(0.98337f);   // E[count] ~= 320, window [200,1024]

    if (tid == 0) scnt = 0;
    __syncthreads();

    for (int i = tid; i < NPAD; i += NT) {    // padded: warp-uniform trip count
        bool inb = (i < NV4);
        uint4 v = inb ? srow[i] : make_uint4(0u, 0u, 0u, 0u);
        uint32_t vals[4] = {v.x, v.y, v.z, v.w};
        #pragma unroll
        for (int j = 0; j < 4; ++j) {
            bool p = inb && (vals[j] >= T);
            unsigned m = __ballot_sync(0xFFFFFFFFu, p);
            if (m) {                           // uniform across warp
                int leader = __ffs(m) - 1;
                int base = 0;
                if (lane == leader) base = atomicAdd(&scnt, __popc(m));
                base = __shfl_sync(0xFFFFFFFFu, base, leader);
                if (p) {
                    int pos = base + __popc(m & ((1u << lane) - 1u));
                    if (pos < CAP)
                        cand[pos] = mk_key(vals[j], (uint32_t)(i * 4 + j));
                }
            }
        }
    }
    __syncthreads();
    int M = scnt;

    // ---------------- 2. Exact fallback (statistically never taken) ------------
    if (M < KTOP || M > CAP) {
        // row max
        uint32_t mymax = 0u;
        for (int i = tid; i < NV4; i += NT) {
            uint4 v = srow[i];
            mymax = max(mymax, max(max(v.x, v.y), max(v.z, v.w)));
        }
        #pragma unroll
        for (int o = 16; o; o >>= 1)
            mymax = max(mymax, __shfl_xor_sync(0xFFFFFFFFu, mymax, o));
        if (lane == 0) red[wid] = mymax;
        __syncthreads();
        if (tid == 0) {
            uint32_t mm = red[0];
            for (int w = 1; w < NT / 32; ++w) mm = max(mm, red[w]);
            red[16] = mm;
        }
        __syncthreads();

        // bisection for T with count(>=T) in [KTOP, CAP]
        uint32_t lo = 0u, hi = red[16];
        T = 0u;
        int bestGe = NN;
        for (int it = 0; it < 34 && lo <= hi; ++it) {
            uint32_t t = lo + ((hi - lo) >> 1);
            int c = 0;
            for (int i = tid; i < NV4; i += NT) {
                uint4 v = srow[i];
                c += (v.x >= t) + (v.y >= t) + (v.z >= t) + (v.w >= t);
            }
            #pragma unroll
            for (int o = 16; o; o >>= 1) c += __shfl_down_sync(0xFFFFFFFFu, c, o);
            __syncthreads();
            if (lane == 0) red[wid] = (uint32_t)c;
            __syncthreads();
            if (tid == 0) {
                int s = 0;
                for (int w = 0; w < NT / 32; ++w) s += (int)red[w];
                red[17] = (uint32_t)s;
            }
            __syncthreads();
            int ge = (int)red[17];
            if (ge >= KTOP) {
                if (ge < bestGe) { bestGe = ge; T = t; }
                if (ge <= CAP) break;
                lo = t + 1;
            } else {
                if (t == 0) break;
                hi = t - 1;
            }
        }

        // recollect at exact T
        __syncthreads();
        if (tid == 0) scnt = 0;
        __syncthreads();
        for (int i = tid; i < NPAD; i += NT) {
            bool inb = (i < NV4);
            uint4 v = inb ? srow[i] : make_uint4(0u, 0u, 0u, 0u);
            uint32_t vals[4] = {v.x, v.y, v.z, v.w};
            #pragma unroll
            for (int j = 0; j < 4; ++j) {
                bool p = inb && (vals[j] >= T);
                unsigned m = __ballot_sync(0xFFFFFFFFu, p);
                if (m) {
                    int leader = __ffs(m) - 1;
                    int base = 0;
                    if (lane == leader) base = atomicAdd(&scnt, __popc(m));
                    base = __shfl_sync(0xFFFFFFFFu, base, leader);
                    if (p) {
                        int pos = base + __popc(m & ((1u << lane) - 1u));
                        if (pos < CAP)
                            cand[pos] = mk_key(vals[j], (uint32_t)(i * 4 + j));
                    }
                }
            }
        }
        __syncthreads();
        M = min(scnt, CAP);
    }

    // ---------------- 3. Bitonic sort descending (pad to pow2 with 0) ----------
    int S = 256;
    while (S < M) S <<= 1;                 // 256 / 512 / 1024
    for (int i = M + tid; i < S; i += NT) cand[i] = 0ull;
    __syncthreads();

    for (int k = 2; k <= S; k <<= 1) {
        for (int j = k >> 1; j > 0; j >>= 1) {
            for (int i = tid; i < S; i += NT) {
                int ixj = i ^ j;
                if (ixj > i) {
                    unsigned long long a  = cand[i];
                    unsigned long long c2 = cand[ixj];
                    bool desc = ((i & k) == 0);
                    if ((a < c2) == desc) { cand[i] = c2; cand[ixj] = a; }
                }
            }
            __syncthreads();
        }
    }

    // ---------------- 4. Gather + decode boxes ---------------------------------
    float x1 = 0.f, y1v = 0.f, x2 = 0.f, y2v = 0.f, area = 0.f, sc = 0.f;
    if (tid < KTOP) {
        unsigned long long key = cand[tid];
        uint32_t idx = 0xFFFFFFFFu - (uint32_t)(key & 0xFFFFFFFFull);
        sc = __uint_as_float((uint32_t)(key >> 32));
        float4 rb = reinterpret_cast<const float4*>(boxes_raw)[(size_t)b * NN + idx];
        float w  = rb.z * 0.5f + 1e-2f;
        float h  = rb.w * 0.5f + 1e-2f;
        float hw = 0.5f * w, hh = 0.5f * h;
        x1  = rb.x - hw;  x2  = rb.x + hw;
        y1v = rb.y - hh;  y2v = rb.y + hh;
        area = (x2 - x1) * (y2v - y1v);     // area from corners (match reference)
        sbox[0][tid] = x1;  sbox[1][tid] = y1v;
        sbox[2][tid] = x2;  sbox[3][tid] = y2v;
        sbox[4][tid] = area;
    }
    __syncthreads();

    // ---------------- 5. IoU max vs higher-scored boxes, pack output -----------
    if (tid < KTOP) {
        float imax = 0.f;
        for (int i = 0; i < tid; ++i) {     // broadcast smem reads
            float xx1 = fmaxf(x1,  sbox[0][i]);
            float yy1 = fmaxf(y1v, sbox[1][i]);
            float xx2 = fminf(x2,  sbox[2][i]);
            float yy2 = fminf(y2v, sbox[3][i]);
            float iw  = fmaxf(xx2 - xx1, 0.f);
            float ih  = fmaxf(yy2 - yy1, 0.f);
            float inter = iw * ih;
            float uni   = area + sbox[4][i] - inter;
            imax = fmaxf(imax, inter / uni);
        }
        float osc = (imax <= 0.5f && sc > 0.05f) ? sc : 0.f;
        size_t o = ((size_t)bc * KTOP + (size_t)tid) * 5;
        out[o + 0] = osc;
        out[o + 1] = x1;
        out[o + 2] = y1v;
        out[o + 3] = x2;
        out[o + 4] = y2v;
    }
}

extern "C" void kernel_launch(void* const* d_in, const int* in_sizes, int n_in,
                              void* d_out, int out_size)
{
    const float* boxes  = (const float*)d_in[0];
    const float* scores = (const float*)d_in[1];
    if (n_in >= 2 && in_sizes[0] > in_sizes[1]) {   // defensive order check
        boxes  = (const float*)d_in[1];
        scores = (const float*)d_in[0];
    }
    (void)out_size;
    fastnms_kernel<<<NB * NC, NT>>>(boxes, scores, (float*)d_out);
}

// round 4
// speedup vs baseline: 4.6900x; 1.7583x over previous
#include <cuda_runtime.h>
#include <stdint.h>

// YOLACT-550 Fast-NMS, GB300 sm_103a — round 3
// B=16, C=80, N=19248, TOP_K=200
// One CTA per (image, class) row. Compare-only scan with per-survivor smem
// atomic push (statistical threshold + exact bisection fallback), 512-wide
// bitonic key sort, division-free triangular suppression, coalesced output.

#define NB   16
#define NC   80
#define NN   19248
#define NV4  4812            // NN/4
#define KTOP 200
#define CAP  512
#define NT   256

__device__ __forceinline__ unsigned long long mk_key(uint32_t v, uint32_t idx) {
    // descending value, ascending index on ties (matches jax.lax.top_k)
    return ((unsigned long long)v << 32) | (unsigned long long)(0xFFFFFFFFu - idx);
}

__global__ __launch_bounds__(NT, 6)
void fastnms_kernel(const float* __restrict__ boxes_raw,
                    const float* __restrict__ scores,
                    float* __restrict__ out)
{
    __shared__ unsigned long long cand[CAP];   // keys; later reused as output stage
    __shared__ float4   sboxv[KTOP];           // x1,y1,x2,y2
    __shared__ float    sar[KTOP];             // areas
    __shared__ uint32_t red[32];
    __shared__ int scnt;

    const int tid  = threadIdx.x;
    const int lane = tid & 31;
    const int wid  = tid >> 5;
    const int bc   = blockIdx.x;               // b*NC + c
    const int b    = bc / NC;

    const uint4* srow = reinterpret_cast<const uint4*>(scores) + (size_t)bc * NV4;

    // ---------------- 1. Compare-only scan at statistical threshold ------------
    // Scores are non-negative floats: raw-bit unsigned compare == float compare.
    uint32_t T = __float_as_uint(0.98337f);    // E[count] ~= 320, sigma ~= 18

    if (tid == 0) scnt = 0;
    __syncthreads();

    #pragma unroll 4
    for (int i = tid; i < NV4; i += NT) {
        uint4 v = srow[i];
        int hits = (v.x >= T) + (v.y >= T) + (v.z >= T) + (v.w >= T);
        if (hits) {                            // rare (~6.4% of uint4s)
            uint32_t vals[4] = {v.x, v.y, v.z, v.w};
            #pragma unroll
            for (int j = 0; j < 4; ++j) {
                if (vals[j] >= T) {
                    int p = atomicAdd(&scnt, 1);
                    if (p < CAP) cand[p] = mk_key(vals[j], (uint32_t)(4 * i + j));
                }
            }
        }
    }
    __syncthreads();
    int M = scnt;

    // ---------------- 2. Exact fallback (statistically never taken) ------------
    if (M < KTOP || M > CAP) {
        uint32_t mymax = 0u;
        for (int i = tid; i < NV4; i += NT) {
            uint4 v = srow[i];
            mymax = max(mymax, max(max(v.x, v.y), max(v.z, v.w)));
        }
        #pragma unroll
        for (int o = 16; o; o >>= 1)
            mymax = max(mymax, __shfl_xor_sync(0xFFFFFFFFu, mymax, o));
        if (lane == 0) red[wid] = mymax;
        __syncthreads();
        if (tid == 0) {
            uint32_t mm = red[0];
            for (int w = 1; w < NT / 32; ++w) mm = max(mm, red[w]);
            red[16] = mm;
        }
        __syncthreads();

        uint32_t lo = 0u, hi = red[16];
        T = 0u;
        int bestGe = NN;
        for (int it = 0; it < 34 && lo <= hi; ++it) {
            uint32_t t = lo + ((hi - lo) >> 1);
            int c = 0;
            for (int i = tid; i < NV4; i += NT) {
                uint4 v = srow[i];
                c += (v.x >= t) + (v.y >= t) + (v.z >= t) + (v.w >= t);
            }
            #pragma unroll
            for (int o = 16; o; o >>= 1) c += __shfl_down_sync(0xFFFFFFFFu, c, o);
            __syncthreads();
            if (lane == 0) red[wid] = (uint32_t)c;
            __syncthreads();
            if (tid == 0) {
                int s = 0;
                for (int w = 0; w < NT / 32; ++w) s += (int)red[w];
                red[17] = (uint32_t)s;
            }
            __syncthreads();
            int ge = (int)red[17];
            if (ge >= KTOP) {
                if (ge < bestGe) { bestGe = ge; T = t; }
                if (ge <= CAP) break;
                lo = t + 1;
            } else {
                if (t == 0) break;
                hi = t - 1;
            }
        }

        __syncthreads();
        if (tid == 0) scnt = 0;
        __syncthreads();
        for (int i = tid; i < NV4; i += NT) {
            uint4 v = srow[i];
            if ((v.x >= T) + (v.y >= T) + (v.z >= T) + (v.w >= T)) {
                uint32_t vals[4] = {v.x, v.y, v.z, v.w};
                #pragma unroll
                for (int j = 0; j < 4; ++j) {
                    if (vals[j] >= T) {
                        int p = atomicAdd(&scnt, 1);
                        if (p < CAP) cand[p] = mk_key(vals[j], (uint32_t)(4 * i + j));
                    }
                }
            }
        }
        __syncthreads();
        M = min(scnt, CAP);
    }

    // ---------------- 3. Bitonic sort descending (pad to pow2 with 0) ----------
    int S = (M <= 256) ? 256 : 512;
    for (int i = M + tid; i < S; i += NT) cand[i] = 0ull;
    __syncthreads();

    for (int k = 2; k <= S; k <<= 1) {
        for (int j = k >> 1; j > 0; j >>= 1) {
            for (int i = tid; i < S; i += NT) {
                int ixj = i ^ j;
                if (ixj > i) {
                    unsigned long long a  = cand[i];
                    unsigned long long c2 = cand[ixj];
                    bool desc = ((i & k) == 0);
                    if ((a < c2) == desc) { cand[i] = c2; cand[ixj] = a; }
                }
            }
            __syncthreads();
        }
    }

    // ---------------- 4. Gather + decode boxes ---------------------------------
    float x1 = 0.f, y1v = 0.f, x2 = 0.f, y2v = 0.f, area = 0.f, sc = 0.f;
    if (tid < KTOP) {
        unsigned long long key = cand[tid];
        uint32_t idx = 0xFFFFFFFFu - (uint32_t)(key & 0xFFFFFFFFull);
        sc = __uint_as_float((uint32_t)(key >> 32));
        float4 rb = reinterpret_cast<const float4*>(boxes_raw)[(size_t)b * NN + idx];
        float w  = rb.z * 0.5f + 1e-2f;
        float h  = rb.w * 0.5f + 1e-2f;
        float hw = 0.5f * w, hh = 0.5f * h;
        x1  = rb.x - hw;  x2  = rb.x + hw;
        y1v = rb.y - hh;  y2v = rb.y + hh;
        area = (x2 - x1) * (y2v - y1v);        // area from corners (match reference)
        sboxv[tid] = make_float4(x1, y1v, x2, y2v);
        sar[tid]   = area;
    }
    __syncthreads();

    // ---------------- 5. Division-free suppression ------------------------------
    // iou <= 0.5  <=>  2*inter <= union  <=>  3*inter <= area_i + area_j
    bool keep = true;
    if (tid < KTOP) {
        for (int i = 0; i < tid; ++i) {
            float4 bi = sboxv[i];                       // LDS.128 broadcast
            float iw  = fminf(x2,  bi.z) - fmaxf(x1,  bi.x);
            float ih  = fminf(y2v, bi.w) - fmaxf(y1v, bi.y);
            iw = fmaxf(iw, 0.f);
            ih = fmaxf(ih, 0.f);
            float inter = iw * ih;
            keep = keep && (3.0f * inter <= area + sar[i]);
        }
    }
    __syncthreads();                                    // cand reuse below

    // ---------------- 6. Stage + coalesced output write -------------------------
    float* stage = reinterpret_cast<float*>(cand);      // 4KB >= 200*5*4B
    if (tid < KTOP) {
        float osc = (keep && sc > 0.05f) ? sc : 0.f;
        stage[tid * 5 + 0] = osc;
        stage[tid * 5 + 1] = x1;
        stage[tid * 5 + 2] = y1v;
        stage[tid * 5 + 3] = x2;
        stage[tid * 5 + 4] = y2v;
    }
    __syncthreads();

    {   // 1000 floats = 250 uint4, rows are 4KB-aligned in out
        uint4* dst = reinterpret_cast<uint4*>(out + (size_t)bc * (KTOP * 5));
        const uint4* src = reinterpret_cast<const uint4*>(stage);
        if (tid < 250) dst[tid] = src[tid];
    }
}

extern "C" void kernel_launch(void* const* d_in, const int* in_sizes, int n_in,
                              void* d_out, int out_size)
{
    const float* boxes  = (const float*)d_in[0];
    const float* scores = (const float*)d_in[1];
    if (n_in >= 2 && in_sizes[0] > in_sizes[1]) {   // defensive order check
        boxes  = (const float*)d_in[1];
        scores = (const float*)d_in[0];
    }
    (void)out_size;
    fastnms_kernel<<<NB * NC, NT>>>(boxes, scores, (float*)d_out);
}

// round 5
// speedup vs baseline: 4.8521x; 1.0346x over previous
#include <cuda_runtime.h>
#include <stdint.h>

// YOLACT-550 Fast-NMS, GB300 sm_103a — round 4
// One CTA per (image,class) row. Compare-only streaming scan (statistical
// threshold + exact bisection fallback), 512-wide bitonic sort with
// one-CE-per-thread indexing, warp-balanced division-free suppression,
// coalesced staged output.

#define NB   16
#define NC   80
#define NN   19248
#define NV4  4812            // NN/4
#define KTOP 200
#define CAP  512
#define NT   256
#define NWARP (NT/32)

__device__ __forceinline__ unsigned long long mk_key(uint32_t v, uint32_t idx) {
    // descending value, ascending index on ties (matches jax.lax.top_k)
    return ((unsigned long long)v << 32) | (unsigned long long)(0xFFFFFFFFu - idx);
}

__global__ __launch_bounds__(NT, 6)
void fastnms_kernel(const float* __restrict__ boxes_raw,
                    const float* __restrict__ scores,
                    float* __restrict__ out)
{
    __shared__ unsigned long long cand[CAP];   // keys; later reused as output stage
    __shared__ float4   sboxv[KTOP];           // x1,y1,x2,y2
    __shared__ float    sar[KTOP];             // areas
    __shared__ uint32_t keepf[KTOP];
    __shared__ uint32_t red[32];
    __shared__ int scnt;

    const int tid  = threadIdx.x;
    const int lane = tid & 31;
    const int wid  = tid >> 5;
    const int bc   = blockIdx.x;               // b*NC + c
    const int b    = bc / NC;

    const uint4* srow = reinterpret_cast<const uint4*>(scores) + (size_t)bc * NV4;

    // ---------------- 1. Compare-only streaming scan at statistical threshold --
    // Scores are non-negative floats: raw-bit unsigned compare == float compare.
    uint32_t T = __float_as_uint(0.98337f);    // E[count] ~= 320, sigma ~= 18

    if (tid == 0) scnt = 0;
    __syncthreads();

    #pragma unroll 4
    for (int i = tid; i < NV4; i += NT) {
        uint4 v = __ldcs(srow + i);            // streaming: single-use data
        if ((v.x >= T) + (v.y >= T) + (v.z >= T) + (v.w >= T)) {  // rare
            uint32_t vals[4] = {v.x, v.y, v.z, v.w};
            #pragma unroll
            for (int j = 0; j < 4; ++j) {
                if (vals[j] >= T) {
                    int p = atomicAdd(&scnt, 1);
                    if (p < CAP) cand[p] = mk_key(vals[j], (uint32_t)(4 * i + j));
                }
            }
        }
    }
    __syncthreads();
    int M = scnt;

    // ---------------- 2. Exact fallback (statistically never taken) ------------
    if (M < KTOP || M > CAP) {
        uint32_t mymax = 0u;
        for (int i = tid; i < NV4; i += NT) {
            uint4 v = srow[i];
            mymax = max(mymax, max(max(v.x, v.y), max(v.z, v.w)));
        }
        #pragma unroll
        for (int o = 16; o; o >>= 1)
            mymax = max(mymax, __shfl_xor_sync(0xFFFFFFFFu, mymax, o));
        if (lane == 0) red[wid] = mymax;
        __syncthreads();
        if (tid == 0) {
            uint32_t mm = red[0];
            for (int w = 1; w < NWARP; ++w) mm = max(mm, red[w]);
            red[16] = mm;
        }
        __syncthreads();

        uint32_t lo = 0u, hi = red[16];
        T = 0u;
        int bestGe = NN;
        for (int it = 0; it < 34 && lo <= hi; ++it) {
            uint32_t t = lo + ((hi - lo) >> 1);
            int c = 0;
            for (int i = tid; i < NV4; i += NT) {
                uint4 v = srow[i];
                c += (v.x >= t) + (v.y >= t) + (v.z >= t) + (v.w >= t);
            }
            #pragma unroll
            for (int o = 16; o; o >>= 1) c += __shfl_down_sync(0xFFFFFFFFu, c, o);
            __syncthreads();
            if (lane == 0) red[wid] = (uint32_t)c;
            __syncthreads();
            if (tid == 0) {
                int s = 0;
                for (int w = 0; w < NWARP; ++w) s += (int)red[w];
                red[17] = (uint32_t)s;
            }
            __syncthreads();
            int ge = (int)red[17];
            if (ge >= KTOP) {
                if (ge < bestGe) { bestGe = ge; T = t; }
                if (ge <= CAP) break;
                lo = t + 1;
            } else {
                if (t == 0) break;
                hi = t - 1;
            }
        }

        __syncthreads();
        if (tid == 0) scnt = 0;
        __syncthreads();
        for (int i = tid; i < NV4; i += NT) {
            uint4 v = srow[i];
            if ((v.x >= T) + (v.y >= T) + (v.z >= T) + (v.w >= T)) {
                uint32_t vals[4] = {v.x, v.y, v.z, v.w};
                #pragma unroll
                for (int j = 0; j < 4; ++j) {
                    if (vals[j] >= T) {
                        int p = atomicAdd(&scnt, 1);
                        if (p < CAP) cand[p] = mk_key(vals[j], (uint32_t)(4 * i + j));
                    }
                }
            }
        }
        __syncthreads();
        M = min(scnt, CAP);
    }

    // ---------------- 3. Bitonic sort, descending, S=512, 1 CE/thread/round ----
    for (int i = M + tid; i < CAP; i += NT) cand[i] = 0ull;   // pad
    __syncthreads();

    #pragma unroll 1
    for (int k = 2; k <= CAP; k <<= 1) {
        #pragma unroll 1
        for (int j = k >> 1; j > 0; j >>= 1) {
            int i   = 2 * tid - (tid & (j - 1));   // exactly S/2 = NT CEs
            int ixj = i + j;
            unsigned long long a  = cand[i];
            unsigned long long c2 = cand[ixj];
            bool desc = ((i & k) == 0);
            if ((a < c2) == desc) { cand[i] = c2; cand[ixj] = a; }
            __syncthreads();
        }
    }

    // ---------------- 4. Gather + decode boxes ---------------------------------
    float x1 = 0.f, y1v = 0.f, x2 = 0.f, y2v = 0.f, sc = 0.f;
    if (tid < KTOP) {
        unsigned long long key = cand[tid];
        uint32_t idx = 0xFFFFFFFFu - (uint32_t)(key & 0xFFFFFFFFull);
        sc = __uint_as_float((uint32_t)(key >> 32));
        float4 rb = __ldg(reinterpret_cast<const float4*>(boxes_raw) + (size_t)b * NN + idx);
        float w  = rb.z * 0.5f + 1e-2f;
        float h  = rb.w * 0.5f + 1e-2f;
        float hw = 0.5f * w, hh = 0.5f * h;
        x1  = rb.x - hw;  x2  = rb.x + hw;
        y1v = rb.y - hh;  y2v = rb.y + hh;
        sboxv[tid] = make_float4(x1, y1v, x2, y2v);
        sar[tid]   = (x2 - x1) * (y2v - y1v);   // area from corners (match ref)
    }
    __syncthreads();

    // ---------------- 5. Warp-balanced division-free suppression ---------------
    // iou <= 0.5  <=>  2*inter <= union  <=>  3*inter <= area_i + area_j
    for (int j = wid; j < KTOP; j += NWARP) {
        float4 bj = sboxv[j];                   // same addr across warp: broadcast
        float  aj = sar[j];
        bool sup = false;
        for (int i = lane; i < j; i += 32) {
            float4 bi = sboxv[i];
            float iw = fminf(bj.z, bi.z) - fmaxf(bj.x, bi.x);
            float ih = fminf(bj.w, bi.w) - fmaxf(bj.y, bi.y);
            iw = fmaxf(iw, 0.f);
            ih = fmaxf(ih, 0.f);
            sup = sup || (3.0f * (iw * ih) > aj + sar[i]);
        }
        sup = __any_sync(0xFFFFFFFFu, sup);
        if (lane == 0) keepf[j] = sup ? 0u : 1u;
    }
    __syncthreads();                            // also guards cand reuse below

    // ---------------- 6. Stage + coalesced output write ------------------------
    float* stage = reinterpret_cast<float*>(cand);   // 4KB >= 200*5*4B
    if (tid < KTOP) {
        float osc = (keepf[tid] && sc > 0.05f) ? sc : 0.f;
        stage[tid * 5 + 0] = osc;
        stage[tid * 5 + 1] = x1;
        stage[tid * 5 + 2] = y1v;
        stage[tid * 5 + 3] = x2;
        stage[tid * 5 + 4] = y2v;
    }
    __syncthreads();

    {   // 1000 floats = 250 uint4 per row
        uint4* dst = reinterpret_cast<uint4*>(out + (size_t)bc * (KTOP * 5));
        const uint4* src = reinterpret_cast<const uint4*>(stage);
        if (tid < 250) dst[tid] = src[tid];
    }
}

extern "C" void kernel_launch(void* const* d_in, const int* in_sizes, int n_in,
                              void* d_out, int out_size)
{
    const float* boxes  = (const float*)d_in[0];
    const float* scores = (const float*)d_in[1];
    if (n_in >= 2 && in_sizes[0] > in_sizes[1]) {   // defensive order check
        boxes  = (const float*)d_in[1];
        scores = (const float*)d_in[0];
    }
    (void)out_size;
    fastnms_kernel<<<NB * NC, NT>>>(boxes, scores, (float*)d_out);
}